// round 2
// baseline (speedup 1.0000x reference)
#include <cuda_runtime.h>

// Problem dims (fixed by the dataset)
#define NB   64      // batch
#define NC   256     // channels
#define NCI  128     // inner channels
#define NTOK 256     // 16x16 tokens
#define NH   64      // spatial H=W

// -------------------- device scratch (no allocation allowed) --------------------
__device__ float g_xp  [NB * NC  * NTOK];   // pooled input  [b][c][tok]   16.8 MB
__device__ float g_W   [384 * NC];          // concat theta/phi/g weights
__device__ float g_bias[384];
__device__ float g_proj[NB * 384 * NTOK];   // theta(0:128)|phi(128:256)|g(256:384) per batch, [r][tok]
__device__ float g_attn[NB * NTOK * NTOK];  // logits -> softmax in place
__device__ float g_agg [NB * NCI * NTOK];   // aggT [cc][tok]

// -------------------- weight concat --------------------
__global__ void concat_weights(const float* __restrict__ tw, const float* __restrict__ tb,
                               const float* __restrict__ pw, const float* __restrict__ pb,
                               const float* __restrict__ gw, const float* __restrict__ gb) {
    int idx = blockIdx.x * 256 + threadIdx.x;
    if (idx < 384 * 256) {
        int r = idx >> 8;
        float v;
        if (r < 128)      v = tw[idx];
        else if (r < 256) v = pw[idx - 128 * 256];
        else              v = gw[idx - 256 * 256];
        g_W[idx] = v;
    }
    if (idx < 384) {
        float v;
        if (idx < 128)      v = tb[idx];
        else if (idx < 256) v = pb[idx - 128];
        else                v = gb[idx - 256];
        g_bias[idx] = v;
    }
}

// -------------------- 4x4 average pool (64x64 -> 16x16) --------------------
// one thread per pooled output element; float4 row loads, fully coalesced
__global__ void pool_kernel(const float* __restrict__ x) {
    int idx = blockIdx.x * 256 + threadIdx.x;      // < NB*NC*NTOK
    int tok = idx & 255;
    int bc  = idx >> 8;
    int ph = tok >> 4, pw = tok & 15;
    const float* base = x + ((long)bc * NH + ph * 4) * NH + pw * 4;
    float s = 0.f;
#pragma unroll
    for (int r = 0; r < 4; r++) {
        float4 v = *(const float4*)(base + r * NH);
        s += v.x + v.y + v.z + v.w;
    }
    g_xp[idx] = s * 0.0625f;
}

// -------------------- generic tiled SGEMM --------------------
// C[m][n] = sum_k A[m][k]*B[k][n]   (logical), per batch (blockIdx.z)
// A_KC: A stored [M][K] (k contiguous) -> transpose into smem.  else stored [K][M] (m contig), direct.
// B_KC: B stored [N][K] (k contiguous) -> transpose into smem.  else stored [K][N] (n contig), direct.
// EPI 0: C = acc        EPI 1: C = acc + bias[m]
// EPI 2: v = acc + bias[m] + resid[b][m][n]; nearest-upsample 4x4 into dout (skip C entirely)
// Tiles: BM=BN=64, BK=16, 256 threads, 4x4 register tile. All dims divide tiles exactly.
template<bool A_KC, bool B_KC, int EPI>
__global__ void __launch_bounds__(256) gemm_k(
    const float* __restrict__ Ag, const float* __restrict__ Bg,
    float* __restrict__ Cg, int M, int N, int K,
    int aB, int bB, int cB,
    const float* __restrict__ bias, const float* __restrict__ resid,
    float* __restrict__ dout)
{
    __shared__ float As[16][68];
    __shared__ float Bs[16][68];
    int b = blockIdx.z;
    const float* A  = Ag + (long)b * aB;
    const float* Bp = Bg + (long)b * bB;
    int m0 = blockIdx.y << 6, n0 = blockIdx.x << 6;
    int tid = threadIdx.x;
    int tx = tid & 15, ty = tid >> 4;
    float acc[4][4] = {};

    for (int k0 = 0; k0 < K; k0 += 16) {
        if (A_KC) {
            int m = tid >> 2, kq = (tid & 3) << 2;
            float4 v = *(const float4*)(A + (long)(m0 + m) * K + k0 + kq);
            As[kq + 0][m] = v.x; As[kq + 1][m] = v.y;
            As[kq + 2][m] = v.z; As[kq + 3][m] = v.w;
        } else {
            int k = tid >> 4, mq = (tid & 15) << 2;
            *(float4*)&As[k][mq] = *(const float4*)(A + (long)(k0 + k) * M + m0 + mq);
        }
        if (B_KC) {
            int n = tid >> 2, kq = (tid & 3) << 2;
            float4 v = *(const float4*)(Bp + (long)(n0 + n) * K + k0 + kq);
            Bs[kq + 0][n] = v.x; Bs[kq + 1][n] = v.y;
            Bs[kq + 2][n] = v.z; Bs[kq + 3][n] = v.w;
        } else {
            int k = tid >> 4, nq = (tid & 15) << 2;
            *(float4*)&Bs[k][nq] = *(const float4*)(Bp + (long)(k0 + k) * N + n0 + nq);
        }
        __syncthreads();
#pragma unroll
        for (int k = 0; k < 16; k++) {
            float4 av = *(const float4*)&As[k][ty << 2];
            float4 bv = *(const float4*)&Bs[k][tx << 2];
            float a[4] = {av.x, av.y, av.z, av.w};
            float bb[4] = {bv.x, bv.y, bv.z, bv.w};
#pragma unroll
            for (int i = 0; i < 4; i++)
#pragma unroll
                for (int j = 0; j < 4; j++)
                    acc[i][j] = fmaf(a[i], bb[j], acc[i][j]);
        }
        __syncthreads();
    }

    if (EPI <= 1) {
#pragma unroll
        for (int i = 0; i < 4; i++) {
            int m = m0 + (ty << 2) + i;
            float bi = (EPI == 1) ? bias[m] : 0.f;
            float4 w;
            w.x = acc[i][0] + bi; w.y = acc[i][1] + bi;
            w.z = acc[i][2] + bi; w.w = acc[i][3] + bi;
            *(float4*)(Cg + (long)b * cB + (long)m * N + n0 + (tx << 2)) = w;
        }
    } else {
        // out conv + bias + residual(xp) + nearest 4x4 upsample straight to d_out
#pragma unroll
        for (int i = 0; i < 4; i++) {
            int c = m0 + (ty << 2) + i;
            float bi = bias[c];
            const float* rrow = resid + ((long)b * NC + c) * NTOK;
            float* crow = dout + ((long)b * NC + c) * (NH * NH);
#pragma unroll
            for (int j = 0; j < 4; j++) {
                int t = n0 + (tx << 2) + j;
                float v = acc[i][j] + bi + rrow[t];
                int ph = t >> 4, pw = t & 15;
                float* o = crow + (ph * 4) * NH + pw * 4;
                float4 f = make_float4(v, v, v, v);
                *(float4*)(o)           = f;
                *(float4*)(o + NH)      = f;
                *(float4*)(o + 2 * NH)  = f;
                *(float4*)(o + 3 * NH)  = f;
            }
        }
    }
}

// -------------------- row softmax over 256 elements, in place --------------------
__global__ void softmax_k(float* __restrict__ a) {
    float* row = a + (long)blockIdx.x * NTOK;
    int t = threadIdx.x;
    int lane = t & 31, w = t >> 5;
    float v = row[t];

    __shared__ float sred[8];
    __shared__ float bmax, bsum;

    float m = v;
#pragma unroll
    for (int o = 16; o > 0; o >>= 1) m = fmaxf(m, __shfl_xor_sync(0xffffffffu, m, o));
    if (lane == 0) sred[w] = m;
    __syncthreads();
    if (t == 0) {
        float mm = sred[0];
#pragma unroll
        for (int i = 1; i < 8; i++) mm = fmaxf(mm, sred[i]);
        bmax = mm;
    }
    __syncthreads();

    float e = __expf(v - bmax);
    float s = e;
#pragma unroll
    for (int o = 16; o > 0; o >>= 1) s += __shfl_xor_sync(0xffffffffu, s, o);
    if (lane == 0) sred[w] = s;
    __syncthreads();
    if (t == 0) {
        float ss = 0.f;
#pragma unroll
        for (int i = 0; i < 8; i++) ss += sred[i];
        bsum = 1.f / ss;
    }
    __syncthreads();

    row[t] = e * bsum;
}

// -------------------- launch --------------------
extern "C" void kernel_launch(void* const* d_in, const int* in_sizes, int n_in,
                              void* d_out, int out_size) {
    (void)in_sizes; (void)n_in; (void)out_size;
    const float* x  = (const float*)d_in[0];
    const float* tw = (const float*)d_in[1];
    const float* tb = (const float*)d_in[2];
    const float* pw = (const float*)d_in[3];
    const float* pb = (const float*)d_in[4];
    const float* gw = (const float*)d_in[5];
    const float* gb = (const float*)d_in[6];
    const float* ow = (const float*)d_in[7];
    const float* ob = (const float*)d_in[8];
    float* out = (float*)d_out;

    float *xp, *W, *bias, *proj, *attn, *agg;
    cudaGetSymbolAddress((void**)&xp,   g_xp);
    cudaGetSymbolAddress((void**)&W,    g_W);
    cudaGetSymbolAddress((void**)&bias, g_bias);
    cudaGetSymbolAddress((void**)&proj, g_proj);
    cudaGetSymbolAddress((void**)&attn, g_attn);
    cudaGetSymbolAddress((void**)&agg,  g_agg);

    // 1. concat weights/biases into one [384,256] matrix
    concat_weights<<<384, 256>>>(tw, tb, pw, pb, gw, gb);

    // 2. adaptive avg pool 64x64 -> 16x16
    pool_kernel<<<(NB * NC * NTOK) / 256, 256>>>(x);

    // 3. projections: proj[b][384][tok] = W @ xp[b] + bias
    //    A = W [384][256] k-contig; B = xp [256c][256tok] n-contig; EPI=bias
    gemm_k<true, false, 1><<<dim3(4, 6, NB), 256>>>(
        W, xp, proj, 384, NTOK, NC, 0, NC * NTOK, 384 * NTOK, bias, nullptr, nullptr);

    // 4. logits[b][i][j] = theta[:,i] . phi[:,j]
    //    A = theta stored [c][i] (m-contig); B = phi stored [c][j] (n-contig)
    gemm_k<false, false, 0><<<dim3(4, 4, NB), 256>>>(
        proj, proj + NCI * NTOK, attn, NTOK, NTOK, NCI,
        384 * NTOK, 384 * NTOK, NTOK * NTOK, nullptr, nullptr, nullptr);

    // 5. softmax over j, in place
    softmax_k<<<NB * NTOK, 256>>>(attn);

    // 6. aggT[b][cc][i] = sum_j g[cc][j] * attn[i][j]
    //    A = g stored [cc][j] (k-contig); B = attn stored [i][j] (k-contig)
    gemm_k<true, true, 0><<<dim3(4, 2, NB), 256>>>(
        proj + 2 * NCI * NTOK, attn, agg, NCI, NTOK, NTOK,
        384 * NTOK, NTOK * NTOK, NCI * NTOK, nullptr, nullptr, nullptr);

    // 7. out conv + bias + residual + nearest upsample -> d_out
    //    A = out_w [256][128] k-contig; B = aggT [cc][i] n-contig
    gemm_k<true, false, 2><<<dim3(4, 4, NB), 256>>>(
        ow, agg, nullptr, NC, NTOK, NCI,
        0, NCI * NTOK, 0, ob, xp, out);
}

// round 3
// speedup vs baseline: 1.4852x; 1.4852x over previous
#include <cuda_runtime.h>
#include <cstdint>

// Problem dims (fixed)
#define NB   64
#define NC   256
#define NCI  128
#define NTOK 256
#define NH   64

// -------------------- device scratch --------------------
__device__ float g_xp  [NB * NC  * NTOK];   // pooled [b][c][tok]
__device__ float g_Wtp [NC * 256];          // [c][r] r = theta(0:128)|phi(128:256)  (transposed weights)
__device__ float g_gwT [NC * NCI];          // [c][cc]
__device__ float g_owT [NCI * NC];          // [cc][C]
__device__ float g_btp [256];               // theta_b|phi_b
__device__ float g_proj[NB * 256 * NTOK];   // theta|phi per batch, [r][tok]
__device__ float g_gT  [NB * NTOK * NCI];   // [tok][cc]
__device__ float g_attn[NB * NTOK * NTOK];  // attnT [j][i], softmax over j in place
__device__ float g_agg [NB * NCI * NTOK];   // aggT [cc][tok]

// -------------------- helpers --------------------
__device__ __forceinline__ uint32_t f2tf32(float f) {
    uint32_t r;
    asm("cvt.rna.tf32.f32 %0, %1;" : "=r"(r) : "f"(f));
    return r;
}

__device__ __forceinline__ void mma_tf32(float (&c)[4],
                                         uint32_t a0, uint32_t a1, uint32_t a2, uint32_t a3,
                                         uint32_t b0, uint32_t b1) {
    asm volatile(
        "mma.sync.aligned.m16n8k8.row.col.f32.tf32.tf32.f32 "
        "{%0,%1,%2,%3},{%4,%5,%6,%7},{%8,%9},{%0,%1,%2,%3};\n"
        : "+f"(c[0]), "+f"(c[1]), "+f"(c[2]), "+f"(c[3])
        : "r"(a0), "r"(a1), "r"(a2), "r"(a3), "r"(b0), "r"(b1));
}

// -------------------- weight prep (tiny, once per call) --------------------
__global__ void concat_weights(const float* __restrict__ tw, const float* __restrict__ tb,
                               const float* __restrict__ pw, const float* __restrict__ pb,
                               const float* __restrict__ gw, const float* __restrict__ ow) {
    int idx = blockIdx.x * 256 + threadIdx.x;   // 0 .. 131071
    if (idx < 65536) {
        // Wtp[c][r] = (r<128 ? tw[r][c] : pw[r-128][c])
        int c = idx >> 8, r = idx & 255;
        g_Wtp[idx] = (r < 128) ? tw[r * NC + c] : pw[(r - 128) * NC + c];
        if (idx < 256) g_btp[idx] = (idx < 128) ? tb[idx] : pb[idx - 128];
    } else if (idx < 65536 + 32768) {
        int j = idx - 65536;               // gwT[c][cc] = gw[cc][c]
        int c = j >> 7, cc = j & 127;
        g_gwT[j] = gw[cc * NC + c];
    } else {
        int j = idx - 65536 - 32768;       // owT[cc][C] = ow[C][cc]
        int cc = j >> 8, C = j & 255;
        g_owT[j] = ow[C * NCI + cc];
    }
}

// -------------------- 4x4 avg pool (64x64 -> 16x16) --------------------
__global__ void pool_kernel(const float* __restrict__ x) {
    int idx = blockIdx.x * 256 + threadIdx.x;
    int tok = idx & 255;
    int bc  = idx >> 8;
    int ph = tok >> 4, pw = tok & 15;
    const float* base = x + ((long)bc * NH + ph * 4) * NH + pw * 4;
    float s = 0.f;
#pragma unroll
    for (int r = 0; r < 4; r++) {
        float4 v = *(const float4*)(base + r * NH);
        s += v.x + v.y + v.z + v.w;
    }
    g_xp[idx] = s * 0.0625f;
}

// -------------------- tf32 tensor-core GEMM --------------------
// C[m][n] = sum_k A[k][m] * B[k][n]   (both operands stored K-major, m/n contiguous)
// BM=BN=64, BK=32, 256 threads (8 warps: 4 in M x 2 in N, warp tile 16x32)
// EPI 0: C=acc   1: C=acc+bias[m]   3: C=acc+bias[n]
// EPI 2: v=acc+bias[m]+resid[b][m][n]; nearest 4x4 upsample into dout
template<int EPI>
__global__ void __launch_bounds__(256) mma_gemm(
    const float* __restrict__ Ag, const float* __restrict__ Bg,
    float* __restrict__ Cg, int M, int N, int K,
    int aB, int bB, int cB,
    const float* __restrict__ bias, const float* __restrict__ resid,
    float* __restrict__ dout)
{
    __shared__ uint32_t As[32][72];
    __shared__ uint32_t Bs[32][72];

    int b = blockIdx.z;
    const float* A = Ag + (long)b * aB;
    const float* B = Bg + (long)b * bB;
    int m0 = blockIdx.y << 6, n0 = blockIdx.x << 6;
    int tid  = threadIdx.x;
    int lane = tid & 31, wid = tid >> 5;
    int wm = (wid & 3) << 4;       // warp m offset (0,16,32,48)
    int wn = (wid >> 2) << 5;      // warp n offset (0,32)
    int lc = lane & 3, lr = lane >> 2;

    float acc[4][4] = {};          // 4 n-tiles x 4 regs

    int kA = tid >> 4;             // 0..15
    int q  = (tid & 15) << 2;      // 0..60

    for (int k0 = 0; k0 < K; k0 += 32) {
        float4 a0 = *(const float4*)(A + (long)(k0 + kA) * M + m0 + q);
        float4 a1 = *(const float4*)(A + (long)(k0 + kA + 16) * M + m0 + q);
        float4 b0 = *(const float4*)(B + (long)(k0 + kA) * N + n0 + q);
        float4 b1 = *(const float4*)(B + (long)(k0 + kA + 16) * N + n0 + q);
        __syncthreads();
        {
            uint4 u;
            u.x = f2tf32(a0.x); u.y = f2tf32(a0.y); u.z = f2tf32(a0.z); u.w = f2tf32(a0.w);
            *(uint4*)&As[kA][q] = u;
            u.x = f2tf32(a1.x); u.y = f2tf32(a1.y); u.z = f2tf32(a1.z); u.w = f2tf32(a1.w);
            *(uint4*)&As[kA + 16][q] = u;
            u.x = f2tf32(b0.x); u.y = f2tf32(b0.y); u.z = f2tf32(b0.z); u.w = f2tf32(b0.w);
            *(uint4*)&Bs[kA][q] = u;
            u.x = f2tf32(b1.x); u.y = f2tf32(b1.y); u.z = f2tf32(b1.z); u.w = f2tf32(b1.w);
            *(uint4*)&Bs[kA + 16][q] = u;
        }
        __syncthreads();

#pragma unroll
        for (int ks = 0; ks < 32; ks += 8) {
            uint32_t fa0 = As[ks + lc][wm + lr];
            uint32_t fa1 = As[ks + lc][wm + lr + 8];
            uint32_t fa2 = As[ks + lc + 4][wm + lr];
            uint32_t fa3 = As[ks + lc + 4][wm + lr + 8];
#pragma unroll
            for (int t = 0; t < 4; t++) {
                uint32_t fb0 = Bs[ks + lc][wn + (t << 3) + lr];
                uint32_t fb1 = Bs[ks + lc + 4][wn + (t << 3) + lr];
                mma_tf32(acc[t], fa0, fa1, fa2, fa3, fb0, fb1);
            }
        }
    }

    int r0 = m0 + wm + lr;      // acc rows r0 and r0+8
    if (EPI != 2) {
        float bm0 = 0.f, bm1 = 0.f;
        if (EPI == 1) { bm0 = bias[r0]; bm1 = bias[r0 + 8]; }
        float* Cb = Cg + (long)b * cB;
#pragma unroll
        for (int t = 0; t < 4; t++) {
            int cn = n0 + wn + (t << 3) + (lc << 1);
            float bn0 = 0.f, bn1 = 0.f;
            if (EPI == 3) { bn0 = bias[cn]; bn1 = bias[cn + 1]; }
            float2 w0 = make_float2(acc[t][0] + bm0 + bn0, acc[t][1] + bm0 + bn1);
            float2 w1 = make_float2(acc[t][2] + bm1 + bn0, acc[t][3] + bm1 + bn1);
            *(float2*)(Cb + (long)r0 * N + cn)       = w0;
            *(float2*)(Cb + (long)(r0 + 8) * N + cn) = w1;
        }
    } else {
        // out conv + bias + residual + nearest 4x4 upsample
#pragma unroll
        for (int rr = 0; rr < 2; rr++) {
            int c = r0 + rr * 8;
            float bi = bias[c];
            const float* rrow = resid + ((long)b * NC + c) * NTOK;
            float* crow = dout + ((long)b * NC + c) * (NH * NH);
#pragma unroll
            for (int t = 0; t < 4; t++) {
#pragma unroll
                for (int jj = 0; jj < 2; jj++) {
                    int tok = n0 + wn + (t << 3) + (lc << 1) + jj;
                    float v = acc[t][rr * 2 + jj] + bi + rrow[tok];
                    int ph = tok >> 4, pw = tok & 15;
                    float* o = crow + (ph * 4) * NH + pw * 4;
                    float4 f = make_float4(v, v, v, v);
                    *(float4*)(o)          = f;
                    *(float4*)(o + NH)     = f;
                    *(float4*)(o + 2 * NH) = f;
                    *(float4*)(o + 3 * NH) = f;
                }
            }
        }
    }
}

// -------------------- transposed softmax --------------------
// a = attnT[b][j][i]; normalize over j for each (b,i). Block: (b, 32-wide i chunk).
__global__ void __launch_bounds__(256) softmaxT_k(float* __restrict__ a) {
    int b  = blockIdx.y;
    int i0 = blockIdx.x << 5;
    int t  = threadIdx.x;
    int il = t & 31, jg = t >> 5;          // 8 j-groups of 32 rows each
    float* base = a + ((long)b * NTOK) * NTOK + i0 + il;

    float v[32];
    float m = -1e30f;
#pragma unroll
    for (int qj = 0; qj < 32; qj++) {
        v[qj] = base[(long)(jg * 32 + qj) * NTOK];
        m = fmaxf(m, v[qj]);
    }
    __shared__ float red[8][32];
    red[jg][il] = m;
    __syncthreads();
    float mm = red[0][il];
#pragma unroll
    for (int g = 1; g < 8; g++) mm = fmaxf(mm, red[g][il]);
    __syncthreads();

    float s = 0.f;
#pragma unroll
    for (int qj = 0; qj < 32; qj++) {
        v[qj] = __expf(v[qj] - mm);
        s += v[qj];
    }
    red[jg][il] = s;
    __syncthreads();
    float ss = 0.f;
#pragma unroll
    for (int g = 0; g < 8; g++) ss += red[g][il];
    float inv = 1.f / ss;
#pragma unroll
    for (int qj = 0; qj < 32; qj++)
        base[(long)(jg * 32 + qj) * NTOK] = v[qj] * inv;
}

// -------------------- launch --------------------
extern "C" void kernel_launch(void* const* d_in, const int* in_sizes, int n_in,
                              void* d_out, int out_size) {
    (void)in_sizes; (void)n_in; (void)out_size;
    const float* x  = (const float*)d_in[0];
    const float* tw = (const float*)d_in[1];
    const float* tb = (const float*)d_in[2];
    const float* pw = (const float*)d_in[3];
    const float* pb = (const float*)d_in[4];
    const float* gw = (const float*)d_in[5];
    const float* gb = (const float*)d_in[6];
    const float* ow = (const float*)d_in[7];
    const float* ob = (const float*)d_in[8];
    float* out = (float*)d_out;

    float *xp, *Wtp, *gwT, *owT, *btp, *proj, *gT, *attn, *agg;
    cudaGetSymbolAddress((void**)&xp,   g_xp);
    cudaGetSymbolAddress((void**)&Wtp,  g_Wtp);
    cudaGetSymbolAddress((void**)&gwT,  g_gwT);
    cudaGetSymbolAddress((void**)&owT,  g_owT);
    cudaGetSymbolAddress((void**)&btp,  g_btp);
    cudaGetSymbolAddress((void**)&proj, g_proj);
    cudaGetSymbolAddress((void**)&gT,   g_gT);
    cudaGetSymbolAddress((void**)&attn, g_attn);
    cudaGetSymbolAddress((void**)&agg,  g_agg);

    // 1. transpose/concat weights
    concat_weights<<<512, 256>>>(tw, tb, pw, pb, gw, ow);

    // 2. pool 64x64 -> 16x16
    pool_kernel<<<(NB * NC * NTOK) / 256, 256>>>(x);

    // 3. theta|phi projection: proj[b][r][tok], M=256 r, N=256 tok, K=256 c
    //    A = Wtp[c][r], B = xp[b][c][tok]; bias over m
    mma_gemm<1><<<dim3(4, 4, NB), 256>>>(
        Wtp, xp, proj, 256, NTOK, NC, 0, NC * NTOK, 256 * NTOK, btp, nullptr, nullptr);

    // 4. g projection (transposed out): gT[b][tok][cc], M=256 tok, N=128 cc, K=256 c
    //    A = xp[b][c][tok], B = gwT[c][cc]; bias over n (g_b)
    mma_gemm<3><<<dim3(2, 4, NB), 256>>>(
        xp, gwT, gT, NTOK, NCI, NC, NC * NTOK, 0, NTOK * NCI, gb, nullptr, nullptr);

    // 5. logitsT: attnT[b][j][i] = sum_c phi[c][j] * theta[c][i], M=256 j, N=256 i, K=128 c
    mma_gemm<0><<<dim3(4, 4, NB), 256>>>(
        proj + NCI * NTOK, proj, attn, NTOK, NTOK, NCI,
        256 * NTOK, 256 * NTOK, NTOK * NTOK, nullptr, nullptr, nullptr);

    // 6. softmax over j (rows of attnT), per column i
    softmaxT_k<<<dim3(8, NB), 256>>>(attn);

    // 7. agg: aggT[b][cc][i] = sum_j gT[j][cc] * attnT[j][i], M=128 cc, N=256 i, K=256 j
    mma_gemm<0><<<dim3(4, 2, NB), 256>>>(
        gT, attn, agg, NCI, NTOK, NTOK,
        NTOK * NCI, NTOK * NTOK, NCI * NTOK, nullptr, nullptr, nullptr);

    // 8. out conv + bias + residual + nearest upsample -> d_out
    //    M=256 C, N=256 tok, K=128 cc: A = owT[cc][C], B = aggT[b][cc][tok]
    mma_gemm<2><<<dim3(4, 4, NB), 256>>>(
        owT, agg, nullptr, NC, NTOK, NCI,
        0, NCI * NTOK, 0, ob, xp, out);
}

// round 4
// speedup vs baseline: 1.5324x; 1.0317x over previous
#include <cuda_runtime.h>
#include <cstdint>

// Problem dims (fixed)
#define NB   64
#define NC   256
#define NCI  128
#define NTOK 256
#define NH   64

// -------------------- device scratch --------------------
__device__ float g_xp  [NB * NC  * NTOK];   // pooled [b][c][tok]
__device__ float g_Wtp [NC * 256];          // [c][r] r = theta|phi (transposed)
__device__ float g_gwT [NC * NCI];          // [c][cc]
__device__ float g_owT [NCI * NC];          // [cc][C]
__device__ float g_btp [256];               // theta_b|phi_b
__device__ float g_proj[NB * 256 * NTOK];   // theta|phi per batch, [r][tok]
__device__ float g_gT  [NB * NTOK * NCI];   // [tok][cc]
__device__ float g_attn[NB * NTOK * NTOK];  // attnT [j][i]
__device__ float g_agg [NB * NCI * NTOK];   // aggT [cc][tok]

// -------------------- helpers --------------------
__device__ __forceinline__ uint32_t f2tf32(float f) {
    uint32_t r;
    asm("cvt.rna.tf32.f32 %0, %1;" : "=r"(r) : "f"(f));
    return r;
}
__device__ __forceinline__ uint4 cvt4(float4 v) {
    uint4 u;
    u.x = f2tf32(v.x); u.y = f2tf32(v.y); u.z = f2tf32(v.z); u.w = f2tf32(v.w);
    return u;
}
__device__ __forceinline__ void mma_tf32(float (&c)[4],
                                         uint32_t a0, uint32_t a1, uint32_t a2, uint32_t a3,
                                         uint32_t b0, uint32_t b1) {
    asm volatile(
        "mma.sync.aligned.m16n8k8.row.col.f32.tf32.tf32.f32 "
        "{%0,%1,%2,%3},{%4,%5,%6,%7},{%8,%9},{%0,%1,%2,%3};\n"
        : "+f"(c[0]), "+f"(c[1]), "+f"(c[2]), "+f"(c[3])
        : "r"(a0), "r"(a1), "r"(a2), "r"(a3), "r"(b0), "r"(b1));
}

// -------------------- weight prep --------------------
__global__ void concat_weights(const float* __restrict__ tw, const float* __restrict__ tb,
                               const float* __restrict__ pw, const float* __restrict__ pb,
                               const float* __restrict__ gw, const float* __restrict__ ow) {
    int idx = blockIdx.x * 256 + threadIdx.x;
    if (idx < 65536) {
        int c = idx >> 8, r = idx & 255;
        g_Wtp[idx] = (r < 128) ? tw[r * NC + c] : pw[(r - 128) * NC + c];
        if (idx < 256) g_btp[idx] = (idx < 128) ? tb[idx] : pb[idx - 128];
    } else if (idx < 65536 + 32768) {
        int j = idx - 65536;
        int c = j >> 7, cc = j & 127;
        g_gwT[j] = gw[cc * NC + c];
    } else {
        int j = idx - 65536 - 32768;
        int cc = j >> 8, C = j & 255;
        g_owT[j] = ow[C * NCI + cc];
    }
}

// -------------------- 4x4 avg pool --------------------
__global__ void pool_kernel(const float* __restrict__ x) {
    int idx = blockIdx.x * 256 + threadIdx.x;
    int tok = idx & 255;
    int bc  = idx >> 8;
    int ph = tok >> 4, pw = tok & 15;
    const float* base = x + ((long)bc * NH + ph * 4) * NH + pw * 4;
    float s = 0.f;
#pragma unroll
    for (int r = 0; r < 4; r++) {
        float4 v = *(const float4*)(base + r * NH);
        s += v.x + v.y + v.z + v.w;
    }
    g_xp[idx] = s * 0.0625f;
}

// -------------------- tf32 tensor-core GEMM, 128x128 CTA tile --------------------
// C[m][n] = sum_k A[k][m] * B[k][n] (both K-major). BM=BN=128, BK=16.
// 256 threads = 8 warps (4 in M x 2 in N); warp tile 32x64. Double-buffered smem.
// EPI 0: C=acc  1: +bias[m]  3: +bias[n]  2: +bias[m]+resid, nearest 4x4 upsample to dout
#define ASTR 136
template<int EPI>
__global__ void __launch_bounds__(256) mma_gemm(
    const float* __restrict__ Ag, const float* __restrict__ Bg,
    float* __restrict__ Cg, int M, int N, int K,
    int aB, int bB, int cB,
    const float* __restrict__ bias, const float* __restrict__ resid,
    float* __restrict__ dout)
{
    __shared__ uint32_t As[2][16][ASTR];
    __shared__ uint32_t Bs[2][16][ASTR];

    int b = blockIdx.z;
    const float* A = Ag + (long)b * aB;
    const float* B = Bg + (long)b * bB;
    int m0 = blockIdx.y << 7, n0 = blockIdx.x << 7;
    int tid  = threadIdx.x;
    int lane = tid & 31, wid = tid >> 5;
    int wm = (wid & 3) << 5;       // 0,32,64,96
    int wn = (wid >> 2) << 6;      // 0,64
    int lc = lane & 3, lr = lane >> 2;

    int kr = tid >> 4;             // 0..15 (k row for staging)
    int c4 = (tid & 15) << 2;      // 0..60 (float4 col offset)

    float acc[2][8][4] = {};

    int nk = K >> 4;

    // prologue: stage block 0
    float4 ra0 = *(const float4*)(A + (long)kr * M + m0 + c4);
    float4 ra1 = *(const float4*)(A + (long)kr * M + m0 + c4 + 64);
    float4 rb0 = *(const float4*)(B + (long)kr * N + n0 + c4);
    float4 rb1 = *(const float4*)(B + (long)kr * N + n0 + c4 + 64);
    *(uint4*)&As[0][kr][c4]      = cvt4(ra0);
    *(uint4*)&As[0][kr][c4 + 64] = cvt4(ra1);
    *(uint4*)&Bs[0][kr][c4]      = cvt4(rb0);
    *(uint4*)&Bs[0][kr][c4 + 64] = cvt4(rb1);
    __syncthreads();

    for (int kb = 0; kb < nk; kb++) {
        int cur = kb & 1;
        if (kb + 1 < nk) {
            long ko = (long)((kb + 1) << 4) + kr;
            ra0 = *(const float4*)(A + ko * M + m0 + c4);
            ra1 = *(const float4*)(A + ko * M + m0 + c4 + 64);
            rb0 = *(const float4*)(B + ko * N + n0 + c4);
            rb1 = *(const float4*)(B + ko * N + n0 + c4 + 64);
        }
#pragma unroll
        for (int ks = 0; ks < 16; ks += 8) {
            uint32_t fa[2][4];
#pragma unroll
            for (int mt = 0; mt < 2; mt++) {
                int mo = wm + (mt << 4) + lr;
                fa[mt][0] = As[cur][ks + lc][mo];
                fa[mt][1] = As[cur][ks + lc][mo + 8];
                fa[mt][2] = As[cur][ks + lc + 4][mo];
                fa[mt][3] = As[cur][ks + lc + 4][mo + 8];
            }
#pragma unroll
            for (int nt = 0; nt < 8; nt++) {
                uint32_t fb0 = Bs[cur][ks + lc][wn + (nt << 3) + lr];
                uint32_t fb1 = Bs[cur][ks + lc + 4][wn + (nt << 3) + lr];
                mma_tf32(acc[0][nt], fa[0][0], fa[0][1], fa[0][2], fa[0][3], fb0, fb1);
                mma_tf32(acc[1][nt], fa[1][0], fa[1][1], fa[1][2], fa[1][3], fb0, fb1);
            }
        }
        if (kb + 1 < nk) {
            int nxt = cur ^ 1;
            *(uint4*)&As[nxt][kr][c4]      = cvt4(ra0);
            *(uint4*)&As[nxt][kr][c4 + 64] = cvt4(ra1);
            *(uint4*)&Bs[nxt][kr][c4]      = cvt4(rb0);
            *(uint4*)&Bs[nxt][kr][c4 + 64] = cvt4(rb1);
            __syncthreads();
        }
    }

    if (EPI != 2) {
        float* Cb = Cg + (long)b * cB;
#pragma unroll
        for (int mt = 0; mt < 2; mt++) {
            int r0 = m0 + wm + (mt << 4) + lr;
            float bm0 = 0.f, bm1 = 0.f;
            if (EPI == 1) { bm0 = bias[r0]; bm1 = bias[r0 + 8]; }
#pragma unroll
            for (int nt = 0; nt < 8; nt++) {
                int cn = n0 + wn + (nt << 3) + (lc << 1);
                float bn0 = 0.f, bn1 = 0.f;
                if (EPI == 3) { bn0 = bias[cn]; bn1 = bias[cn + 1]; }
                float2 w0 = make_float2(acc[mt][nt][0] + bm0 + bn0, acc[mt][nt][1] + bm0 + bn1);
                float2 w1 = make_float2(acc[mt][nt][2] + bm1 + bn0, acc[mt][nt][3] + bm1 + bn1);
                *(float2*)(Cb + (long)r0 * N + cn)       = w0;
                *(float2*)(Cb + (long)(r0 + 8) * N + cn) = w1;
            }
        }
    } else {
        // out conv + bias + residual + nearest 4x4 upsample -> dout
#pragma unroll
        for (int mt = 0; mt < 2; mt++) {
#pragma unroll
            for (int rr = 0; rr < 2; rr++) {
                int c = m0 + wm + (mt << 4) + lr + (rr << 3);
                float bi = bias[c];
                const float* rrow = resid + ((long)b * NC + c) * NTOK;
                float* crow = dout + ((long)b * NC + c) * (NH * NH);
#pragma unroll
                for (int nt = 0; nt < 8; nt++) {
#pragma unroll
                    for (int jj = 0; jj < 2; jj++) {
                        int tok = n0 + wn + (nt << 3) + (lc << 1) + jj;
                        float v = acc[mt][nt][rr * 2 + jj] + bi + rrow[tok];
                        int ph = tok >> 4, pw = tok & 15;
                        float* o = crow + (ph * 4) * NH + pw * 4;
                        float4 f = make_float4(v, v, v, v);
                        *(float4*)(o)          = f;
                        *(float4*)(o + NH)     = f;
                        *(float4*)(o + 2 * NH) = f;
                        *(float4*)(o + 3 * NH) = f;
                    }
                }
            }
        }
    }
}

// -------------------- transposed softmax --------------------
__global__ void __launch_bounds__(256) softmaxT_k(float* __restrict__ a) {
    int b  = blockIdx.y;
    int i0 = blockIdx.x << 5;
    int t  = threadIdx.x;
    int il = t & 31, jg = t >> 5;
    float* base = a + ((long)b * NTOK) * NTOK + i0 + il;

    float v[32];
    float m = -1e30f;
#pragma unroll
    for (int qj = 0; qj < 32; qj++) {
        v[qj] = base[(long)(jg * 32 + qj) * NTOK];
        m = fmaxf(m, v[qj]);
    }
    __shared__ float red[8][32];
    red[jg][il] = m;
    __syncthreads();
    float mm = red[0][il];
#pragma unroll
    for (int g = 1; g < 8; g++) mm = fmaxf(mm, red[g][il]);
    __syncthreads();

    float s = 0.f;
#pragma unroll
    for (int qj = 0; qj < 32; qj++) {
        v[qj] = __expf(v[qj] - mm);
        s += v[qj];
    }
    red[jg][il] = s;
    __syncthreads();
    float ss = 0.f;
#pragma unroll
    for (int g = 0; g < 8; g++) ss += red[g][il];
    float inv = 1.f / ss;
#pragma unroll
    for (int qj = 0; qj < 32; qj++)
        base[(long)(jg * 32 + qj) * NTOK] = v[qj] * inv;
}

// -------------------- launch --------------------
extern "C" void kernel_launch(void* const* d_in, const int* in_sizes, int n_in,
                              void* d_out, int out_size) {
    (void)in_sizes; (void)n_in; (void)out_size;
    const float* x  = (const float*)d_in[0];
    const float* tw = (const float*)d_in[1];
    const float* tb = (const float*)d_in[2];
    const float* pw = (const float*)d_in[3];
    const float* pb = (const float*)d_in[4];
    const float* gw = (const float*)d_in[5];
    const float* gb = (const float*)d_in[6];
    const float* ow = (const float*)d_in[7];
    const float* ob = (const float*)d_in[8];
    float* out = (float*)d_out;

    float *xp, *Wtp, *gwT, *owT, *btp, *proj, *gT, *attn, *agg;
    cudaGetSymbolAddress((void**)&xp,   g_xp);
    cudaGetSymbolAddress((void**)&Wtp,  g_Wtp);
    cudaGetSymbolAddress((void**)&gwT,  g_gwT);
    cudaGetSymbolAddress((void**)&owT,  g_owT);
    cudaGetSymbolAddress((void**)&btp,  g_btp);
    cudaGetSymbolAddress((void**)&proj, g_proj);
    cudaGetSymbolAddress((void**)&gT,   g_gT);
    cudaGetSymbolAddress((void**)&attn, g_attn);
    cudaGetSymbolAddress((void**)&agg,  g_agg);

    concat_weights<<<512, 256>>>(tw, tb, pw, pb, gw, ow);

    pool_kernel<<<(NB * NC * NTOK) / 256, 256>>>(x);

    // theta|phi projection: M=256 r, N=256 tok, K=256 c; bias over m
    mma_gemm<1><<<dim3(2, 2, NB), 256>>>(
        Wtp, xp, proj, 256, NTOK, NC, 0, NC * NTOK, 256 * NTOK, btp, nullptr, nullptr);

    // g projection (transposed): gT[b][tok][cc], M=256, N=128, K=256; bias over n
    mma_gemm<3><<<dim3(1, 2, NB), 256>>>(
        xp, gwT, gT, NTOK, NCI, NC, NC * NTOK, 0, NTOK * NCI, gb, nullptr, nullptr);

    // logitsT: attnT[b][j][i], M=256 j, N=256 i, K=128 c
    mma_gemm<0><<<dim3(2, 2, NB), 256>>>(
        proj + NCI * NTOK, proj, attn, NTOK, NTOK, NCI,
        256 * NTOK, 256 * NTOK, NTOK * NTOK, nullptr, nullptr, nullptr);

    // softmax over j per column i
    softmaxT_k<<<dim3(8, NB), 256>>>(attn);

    // agg: aggT[b][cc][i], M=128 cc, N=256 i, K=256 j
    mma_gemm<0><<<dim3(2, 1, NB), 256>>>(
        gT, attn, agg, NCI, NTOK, NTOK,
        NTOK * NCI, NTOK * NTOK, NCI * NTOK, nullptr, nullptr, nullptr);

    // out conv + bias + residual + nearest upsample -> d_out: M=256 C, N=256 tok, K=128 cc
    mma_gemm<2><<<dim3(2, 2, NB), 256>>>(
        owT, agg, nullptr, NC, NTOK, NCI,
        0, NCI * NTOK, 0, ob, xp, out);
}

// round 6
// speedup vs baseline: 1.5938x; 1.0401x over previous
#include <cuda_runtime.h>
#include <cstdint>

// Problem dims (fixed)
#define NB   64
#define NC   256
#define NCI  128
#define NTOK 256
#define NH   64

// -------------------- device scratch --------------------
__device__ float g_xp  [NB * NC  * NTOK];   // pooled [b][c][tok]
__device__ float g_Wtp [NC * 256];          // [c][r]  r = theta|phi
__device__ float g_gwT [NC * NCI];          // [c][cc]
__device__ float g_owT [NCI * NC];          // [cc][C]
__device__ float g_btp [256];
__device__ float g_proj[NB * 256 * NTOK];   // theta|phi, [r][tok]
__device__ float g_gT  [NB * NTOK * NCI];   // [tok][cc]
__device__ float g_attn[NB * NTOK * NTOK];  // attnT [j][i]
__device__ float g_agg [NB * NCI * NTOK];   // aggT [cc][tok]

// -------------------- mma + cp.async helpers --------------------
__device__ __forceinline__ void mma_tf32(float (&c)[4],
                                         uint32_t a0, uint32_t a1, uint32_t a2, uint32_t a3,
                                         uint32_t b0, uint32_t b1) {
    asm volatile(
        "mma.sync.aligned.m16n8k8.row.col.f32.tf32.tf32.f32 "
        "{%0,%1,%2,%3},{%4,%5,%6,%7},{%8,%9},{%0,%1,%2,%3};\n"
        : "+f"(c[0]), "+f"(c[1]), "+f"(c[2]), "+f"(c[3])
        : "r"(a0), "r"(a1), "r"(a2), "r"(a3), "r"(b0), "r"(b1));
}
#define CPA(dst, src) asm volatile("cp.async.cg.shared.global [%0], [%1], 16;" :: "r"(dst), "l"(src))
#define CPC()         asm volatile("cp.async.commit_group;")
#define CPW(n)        asm volatile("cp.async.wait_group %0;" :: "n"(n))

// -------------------- weight prep --------------------
__global__ void concat_weights(const float* __restrict__ tw, const float* __restrict__ tb,
                               const float* __restrict__ pw, const float* __restrict__ pb,
                               const float* __restrict__ gw, const float* __restrict__ ow) {
    int idx = blockIdx.x * 256 + threadIdx.x;
    if (idx < 65536) {
        int c = idx >> 8, r = idx & 255;
        g_Wtp[idx] = (r < 128) ? tw[r * NC + c] : pw[(r - 128) * NC + c];
        if (idx < 256) g_btp[idx] = (idx < 128) ? tb[idx] : pb[idx - 128];
    } else if (idx < 65536 + 32768) {
        int j = idx - 65536;
        int c = j >> 7, cc = j & 127;
        g_gwT[j] = gw[cc * NC + c];
    } else {
        int j = idx - 65536 - 32768;
        int cc = j >> 8, C = j & 255;
        g_owT[j] = ow[C * NCI + cc];
    }
}

// -------------------- 4x4 avg pool --------------------
__global__ void pool_kernel(const float* __restrict__ x) {
    int idx = blockIdx.x * 256 + threadIdx.x;
    int tok = idx & 255;
    int bc  = idx >> 8;
    int ph = tok >> 4, pw = tok & 15;
    const float* base = x + ((long)bc * NH + ph * 4) * NH + pw * 4;
    float s = 0.f;
#pragma unroll
    for (int r = 0; r < 4; r++) {
        float4 v = *(const float4*)(base + r * NH);
        s += v.x + v.y + v.z + v.w;
    }
    g_xp[idx] = s * 0.0625f;
}

// -------------------- tf32 GEMM, cp.async 4-stage pipeline --------------------
// C[m][n] = sum_k A[k][m]*B[k][n]  (both K-major). BN=128, BK=16, 256 threads.
// BM=128: 8 warps as 4(M)x2(N), warp tile 32x64 (mt=2, nt=8)
// BM= 64: 8 warps as 2(M)x4(N), warp tile 32x32 (mt=2, nt=4)
// Raw fp32 bits into mma.tf32 (HW truncates mantissa) -> no cvt, no reg staging.
// EPI 0: C=acc  1: +bias[m]  3: +bias[n]  2: +bias[m]+resid + nearest 4x4 upsample
template<int EPI, int BM>
__global__ void __launch_bounds__(256, 2) mma_gemm(
    const float* __restrict__ Ag, const float* __restrict__ Bg,
    float* __restrict__ Cg, int M, int N, int K,
    int aB, int bB, int cB,
    const float* __restrict__ bias, const float* __restrict__ resid,
    float* __restrict__ dout)
{
    constexpr int ASTR = (BM == 128) ? 136 : 72;   // floats per k-row (pad: 8 mod 32)
    constexpr int BSTR = 136;
    constexpr int STG  = 4;
    constexpr int AFL  = 16 * ASTR;                // floats per A stage
    constexpr int BFL  = 16 * BSTR;
    constexpr int NT   = (BM == 128) ? 8 : 4;

    extern __shared__ float smem[];                // [STG*AFL | STG*BFL]
    uint32_t su = (uint32_t)__cvta_generic_to_shared(smem);

    int b = blockIdx.z;
    const float* A = Ag + (long)b * aB;
    const float* B = Bg + (long)b * bB;
    int m0 = blockIdx.y * BM, n0 = blockIdx.x << 7;
    int tid  = threadIdx.x;
    int lane = tid & 31, wid = tid >> 5;
    int wm, wn;
    if (BM == 128) { wm = (wid & 3) << 5; wn = (wid >> 2) << 6; }
    else           { wm = (wid & 1) << 5; wn = (wid >> 1) << 5; }
    int lc = lane & 3, lr = lane >> 2;

    int kr = tid >> 4;             // 0..15 staging k-row
    int c4 = (tid & 15) << 2;      // 0..60 staging col (float4)

    uint32_t aw = su + (kr * ASTR + c4) * 4;
    uint32_t bw = su + (STG * AFL + kr * BSTR + c4) * 4;

    float acc[2][NT][4] = {};
    int nk = K >> 4;

    auto issue = [&](int slot, int kb) {
        const float* Ab = A + ((long)(kb << 4) + kr) * M + m0 + c4;
        const float* Bb = B + ((long)(kb << 4) + kr) * N + n0 + c4;
        CPA(aw + slot * (AFL * 4), Ab);
        if (BM == 128) CPA(aw + slot * (AFL * 4) + 256, Ab + 64);
        CPA(bw + slot * (BFL * 4), Bb);
        CPA(bw + slot * (BFL * 4) + 256, Bb + 64);
        CPC();
    };

    issue(0, 0); issue(1, 1); issue(2, 2);

    for (int kb = 0; kb < nk; kb++) {
        CPW(2);
        __syncthreads();
        int slot = kb & 3;
        const uint32_t* Asl = (const uint32_t*)smem + slot * AFL;
        const uint32_t* Bsl = (const uint32_t*)smem + STG * AFL + slot * BFL;
#pragma unroll
        for (int ks = 0; ks < 16; ks += 8) {
            uint32_t fa[2][4];
#pragma unroll
            for (int mt = 0; mt < 2; mt++) {
                int mo = wm + (mt << 4) + lr;
                fa[mt][0] = Asl[(ks + lc) * ASTR + mo];
                fa[mt][1] = Asl[(ks + lc) * ASTR + mo + 8];
                fa[mt][2] = Asl[(ks + lc + 4) * ASTR + mo];
                fa[mt][3] = Asl[(ks + lc + 4) * ASTR + mo + 8];
            }
#pragma unroll
            for (int nt = 0; nt < NT; nt++) {
                int no = wn + (nt << 3) + lr;
                uint32_t fb0 = Bsl[(ks + lc) * BSTR + no];
                uint32_t fb1 = Bsl[(ks + lc + 4) * BSTR + no];
                mma_tf32(acc[0][nt], fa[0][0], fa[0][1], fa[0][2], fa[0][3], fb0, fb1);
                mma_tf32(acc[1][nt], fa[1][0], fa[1][1], fa[1][2], fa[1][3], fb0, fb1);
            }
        }
        __syncthreads();
        if (kb + 3 < nk) issue((kb + 3) & 3, kb + 3);
        else             CPC();
    }

    if (EPI != 2) {
        float* Cb = Cg + (long)b * cB;
#pragma unroll
        for (int mt = 0; mt < 2; mt++) {
            int r0 = m0 + wm + (mt << 4) + lr;   // rows r0 and r0+8 for this mt tile
            float bm0 = 0.f, bm1 = 0.f;
            if (EPI == 1) { bm0 = bias[r0]; bm1 = bias[r0 + 8]; }
#pragma unroll
            for (int nt = 0; nt < NT; nt++) {
                int cn = n0 + wn + (nt << 3) + (lc << 1);
                float bn0 = 0.f, bn1 = 0.f;
                if (EPI == 3) { bn0 = bias[cn]; bn1 = bias[cn + 1]; }
                float2 w0 = make_float2(acc[mt][nt][0] + bm0 + bn0, acc[mt][nt][1] + bm0 + bn1);
                float2 w1 = make_float2(acc[mt][nt][2] + bm1 + bn0, acc[mt][nt][3] + bm1 + bn1);
                *(float2*)(Cb + (long)r0 * N + cn)       = w0;
                *(float2*)(Cb + (long)(r0 + 8) * N + cn) = w1;
            }
        }
    } else {
#pragma unroll
        for (int mt = 0; mt < 2; mt++) {
#pragma unroll
            for (int rr = 0; rr < 2; rr++) {
                int c = m0 + wm + (mt << 4) + lr + (rr << 3);
                float bi = bias[c];
                const float* rrow = resid + ((long)b * NC + c) * NTOK;
                float* crow = dout + ((long)b * NC + c) * (NH * NH);
#pragma unroll
                for (int nt = 0; nt < NT; nt++) {
#pragma unroll
                    for (int jj = 0; jj < 2; jj++) {
                        int tok = n0 + wn + (nt << 3) + (lc << 1) + jj;
                        float v = acc[mt][nt][rr * 2 + jj] + bi + rrow[tok];
                        int ph = tok >> 4, pw = tok & 15;
                        float* o = crow + (ph * 4) * NH + pw * 4;
                        float4 f = make_float4(v, v, v, v);
                        *(float4*)(o)          = f;
                        *(float4*)(o + NH)     = f;
                        *(float4*)(o + 2 * NH) = f;
                        *(float4*)(o + 3 * NH) = f;
                    }
                }
            }
        }
    }
}

// -------------------- transposed softmax --------------------
__global__ void __launch_bounds__(256) softmaxT_k(float* __restrict__ a) {
    int b  = blockIdx.y;
    int i0 = blockIdx.x << 5;
    int t  = threadIdx.x;
    int il = t & 31, jg = t >> 5;
    float* base = a + ((long)b * NTOK) * NTOK + i0 + il;

    float v[32];
    float m = -1e30f;
#pragma unroll
    for (int qj = 0; qj < 32; qj++) {
        v[qj] = base[(long)(jg * 32 + qj) * NTOK];
        m = fmaxf(m, v[qj]);
    }
    __shared__ float red[8][32];
    red[jg][il] = m;
    __syncthreads();
    float mm = red[0][il];
#pragma unroll
    for (int g = 1; g < 8; g++) mm = fmaxf(mm, red[g][il]);
    __syncthreads();

    float s = 0.f;
#pragma unroll
    for (int qj = 0; qj < 32; qj++) {
        v[qj] = __expf(v[qj] - mm);
        s += v[qj];
    }
    red[jg][il] = s;
    __syncthreads();
    float ss = 0.f;
#pragma unroll
    for (int g = 0; g < 8; g++) ss += red[g][il];
    float inv = 1.f / ss;
#pragma unroll
    for (int qj = 0; qj < 32; qj++)
        base[(long)(jg * 32 + qj) * NTOK] = v[qj] * inv;
}

// -------------------- launch --------------------
#define SMEM_128 (4 * (16 * 136 * 4) * 2)                       // 69632 B
#define SMEM_64  (4 * (16 * 72 * 4 + 16 * 136 * 4))             // 53248 B

extern "C" void kernel_launch(void* const* d_in, const int* in_sizes, int n_in,
                              void* d_out, int out_size) {
    (void)in_sizes; (void)n_in; (void)out_size;
    const float* x  = (const float*)d_in[0];
    const float* tw = (const float*)d_in[1];
    const float* tb = (const float*)d_in[2];
    const float* pw = (const float*)d_in[3];
    const float* pb = (const float*)d_in[4];
    const float* gw = (const float*)d_in[5];
    const float* gb = (const float*)d_in[6];
    const float* ow = (const float*)d_in[7];
    const float* ob = (const float*)d_in[8];
    float* out = (float*)d_out;

    float *xp, *Wtp, *gwT, *owT, *btp, *proj, *gT, *attn, *agg;
    cudaGetSymbolAddress((void**)&xp,   g_xp);
    cudaGetSymbolAddress((void**)&Wtp,  g_Wtp);
    cudaGetSymbolAddress((void**)&gwT,  g_gwT);
    cudaGetSymbolAddress((void**)&owT,  g_owT);
    cudaGetSymbolAddress((void**)&btp,  g_btp);
    cudaGetSymbolAddress((void**)&proj, g_proj);
    cudaGetSymbolAddress((void**)&gT,   g_gT);
    cudaGetSymbolAddress((void**)&attn, g_attn);
    cudaGetSymbolAddress((void**)&agg,  g_agg);

    // idempotent, not a stream op (not captured) — call every time, no static guard
    cudaFuncSetAttribute(mma_gemm<1, 128>, cudaFuncAttributeMaxDynamicSharedMemorySize, SMEM_128);
    cudaFuncSetAttribute(mma_gemm<0, 128>, cudaFuncAttributeMaxDynamicSharedMemorySize, SMEM_128);
    cudaFuncSetAttribute(mma_gemm<2, 128>, cudaFuncAttributeMaxDynamicSharedMemorySize, SMEM_128);
    cudaFuncSetAttribute(mma_gemm<3, 64>,  cudaFuncAttributeMaxDynamicSharedMemorySize, SMEM_64);
    cudaFuncSetAttribute(mma_gemm<0, 64>,  cudaFuncAttributeMaxDynamicSharedMemorySize, SMEM_64);

    concat_weights<<<512, 256>>>(tw, tb, pw, pb, gw, ow);
    pool_kernel<<<(NB * NC * NTOK) / 256, 256>>>(x);

    // theta|phi projection: M=256, N=256, K=256; bias over m
    mma_gemm<1, 128><<<dim3(2, 2, NB), 256, SMEM_128>>>(
        Wtp, xp, proj, 256, NTOK, NC, 0, NC * NTOK, 256 * NTOK, btp, nullptr, nullptr);

    // g projection (transposed): gT[b][tok][cc], M=256, N=128, K=256; bias over n
    mma_gemm<3, 64><<<dim3(1, 4, NB), 256, SMEM_64>>>(
        xp, gwT, gT, NTOK, NCI, NC, NC * NTOK, 0, NTOK * NCI, gb, nullptr, nullptr);

    // logitsT: attnT[b][j][i], M=256, N=256, K=128
    mma_gemm<0, 128><<<dim3(2, 2, NB), 256, SMEM_128>>>(
        proj + NCI * NTOK, proj, attn, NTOK, NTOK, NCI,
        256 * NTOK, 256 * NTOK, NTOK * NTOK, nullptr, nullptr, nullptr);

    softmaxT_k<<<dim3(8, NB), 256>>>(attn);

    // agg: aggT[b][cc][i], M=128, N=256, K=256
    mma_gemm<0, 64><<<dim3(2, 2, NB), 256, SMEM_64>>>(
        gT, attn, agg, NCI, NTOK, NTOK,
        NTOK * NCI, NTOK * NTOK, NCI * NTOK, nullptr, nullptr, nullptr);

    // out conv + bias + residual + nearest upsample: M=256, N=256, K=128
    mma_gemm<2, 128><<<dim3(2, 2, NB), 256, SMEM_128>>>(
        owT, agg, nullptr, NC, NTOK, NCI,
        0, NCI * NTOK, 0, ob, xp, out);
}